// round 1
// baseline (speedup 1.0000x reference)
#include <cuda_runtime.h>

#define N_NODES 100000
#define N_EDGES 20000
#define NNZ_E   1600000
#define D       128

// ---------------- scratch (static device allocations; no cudaMalloc) --------
__device__ int   g_cnt_v[N_NODES];
__device__ int   g_cnt_e[N_EDGES];
__device__ int   g_rowptr_v[N_NODES + 1];
__device__ int   g_rowptr_e[N_EDGES + 1];
__device__ int   g_fill_v[N_NODES];
__device__ int   g_fill_e[N_EDGES];
__device__ int   g_csr_v[NNZ_E];    // per-vertex list of incident edges
__device__ int   g_csr_e[NNZ_E];    // per-edge list of incident vertices
__device__ float g_inv_sqrt_dv[N_NODES];
__device__ float g_inv_de[N_EDGES];
__device__ float g_se[N_EDGES];     // s_e = sum of inv_sqrt_dv over edge
__device__ float g_agg[N_EDGES * D];
__device__ float g_ye[N_EDGES * D];

// ---------------- degree counting -------------------------------------------
__global__ void k_zero() {
    int i = blockIdx.x * blockDim.x + threadIdx.x;
    if (i < N_NODES) g_cnt_v[i] = 0;
    if (i < N_EDGES) g_cnt_e[i] = 0;
}

__global__ void k_count(const int* __restrict__ v_idx, const int* __restrict__ e_idx) {
    int i = blockIdx.x * blockDim.x + threadIdx.x;
    if (i < NNZ_E) {
        atomicAdd(&g_cnt_v[v_idx[i]], 1);
        atomicAdd(&g_cnt_e[e_idx[i]], 1);
    }
}

// ---------------- single-block exclusive scan (shfl-based) -------------------
template <int N, bool NODE>
__global__ void k_scan() {
    __shared__ int wsum[32];
    __shared__ int carry_s;
    const int tid = threadIdx.x, lane = tid & 31, wid = tid >> 5;
    if (tid == 0) carry_s = 0;
    __syncthreads();
    for (int base = 0; base < N; base += 1024) {
        int i = base + tid;
        int x;
        if (NODE) x = (i < N) ? g_cnt_v[i] : 0;
        else      x = (i < N) ? g_cnt_e[i] : 0;
        // warp inclusive scan
        int v = x;
        #pragma unroll
        for (int o = 1; o < 32; o <<= 1) {
            int t = __shfl_up_sync(0xffffffffu, v, o);
            if (lane >= o) v += t;
        }
        if (lane == 31) wsum[wid] = v;
        __syncthreads();
        if (wid == 0) {
            int s = wsum[lane];
            #pragma unroll
            for (int o = 1; o < 32; o <<= 1) {
                int t = __shfl_up_sync(0xffffffffu, s, o);
                if (lane >= o) s += t;
            }
            wsum[lane] = s;
        }
        __syncthreads();
        int woff  = wid ? wsum[wid - 1] : 0;
        int incl  = v + woff;
        int carry = carry_s;
        if (i < N) {
            int excl = carry + incl - x;
            if (NODE) {
                g_rowptr_v[i] = excl;
                g_fill_v[i]   = excl;
                g_inv_sqrt_dv[i] = (x > 0) ? rsqrtf((float)x) : 0.0f;
            } else {
                g_rowptr_e[i] = excl;
                g_fill_e[i]   = excl;
                g_inv_de[i]   = (x > 0) ? (1.0f / (float)x) : 0.0f;
            }
        }
        __syncthreads();
        if (tid == 1023) carry_s = carry + wsum[31];   // wsum[31] = tile total
        __syncthreads();
    }
    if (tid == 0) {
        if (NODE) g_rowptr_v[N] = carry_s;
        else      g_rowptr_e[N] = carry_s;
    }
}

// ---------------- CSR fill ---------------------------------------------------
__global__ void k_scatter(const int* __restrict__ v_idx, const int* __restrict__ e_idx) {
    int i = blockIdx.x * blockDim.x + threadIdx.x;
    if (i < NNZ_E) {
        int v = v_idx[i];
        int e = e_idx[i];
        int pe = atomicAdd(&g_fill_e[e], 1);
        g_csr_e[pe] = v;
        int pv = atomicAdd(&g_fill_v[v], 1);
        g_csr_v[pv] = e;
    }
}

// ---------------- Agg[e] = sum_{v in e} a_v * X[v];  s_e = sum a_v -----------
// one warp per hyperedge; lane owns 4 consecutive columns (float4)
__global__ void k_agg(const float* __restrict__ X) {
    int w    = (blockIdx.x * blockDim.x + threadIdx.x) >> 5;
    int lane = threadIdx.x & 31;
    if (w >= N_EDGES) return;
    int beg = g_rowptr_e[w];
    int end = g_rowptr_e[w + 1];
    float4 acc = make_float4(0.f, 0.f, 0.f, 0.f);
    float  s   = 0.f;
    for (int j = beg; j < end; j++) {
        int   v = g_csr_e[j];
        float a = g_inv_sqrt_dv[v];
        float4 x = __ldg((const float4*)(X + (size_t)v * D) + lane);
        acc.x += a * x.x; acc.y += a * x.y; acc.z += a * x.z; acc.w += a * x.w;
        s += a;
    }
    ((float4*)(g_agg + (size_t)w * D))[lane] = acc;
    if (lane == 0) g_se[w] = s;
}

// ---------------- Ye = (Agg @ W + s_e * b) * inv_de --------------------------
// one warp per 4 edge-rows; lane owns 4 output cols; W rows read via L1
__global__ void k_gemm(const float* __restrict__ Wm, const float* __restrict__ bias) {
    int w    = (blockIdx.x * blockDim.x + threadIdx.x) >> 5;
    int lane = threadIdx.x & 31;
    int r0   = w * 4;
    if (r0 >= N_EDGES) return;

    float4 acc0 = make_float4(0.f, 0.f, 0.f, 0.f);
    float4 acc1 = acc0, acc2 = acc0, acc3 = acc0;
    const float* A = g_agg + (size_t)r0 * D;

    #pragma unroll 4
    for (int k = 0; k < D; k++) {
        float4 wk = __ldg((const float4*)(Wm + (size_t)k * D) + lane);
        float a0 = __ldg(A + k);
        float a1 = __ldg(A + D + k);
        float a2 = __ldg(A + 2 * D + k);
        float a3 = __ldg(A + 3 * D + k);
        acc0.x += a0 * wk.x; acc0.y += a0 * wk.y; acc0.z += a0 * wk.z; acc0.w += a0 * wk.w;
        acc1.x += a1 * wk.x; acc1.y += a1 * wk.y; acc1.z += a1 * wk.z; acc1.w += a1 * wk.w;
        acc2.x += a2 * wk.x; acc2.y += a2 * wk.y; acc2.z += a2 * wk.z; acc2.w += a2 * wk.w;
        acc3.x += a3 * wk.x; acc3.y += a3 * wk.y; acc3.z += a3 * wk.z; acc3.w += a3 * wk.w;
    }

    float4 bb = __ldg((const float4*)bias + lane);
    #pragma unroll
    for (int r = 0; r < 4; r++) {
        float4 acc = (r == 0) ? acc0 : (r == 1) ? acc1 : (r == 2) ? acc2 : acc3;
        float se  = g_se[r0 + r];
        float sc  = g_inv_de[r0 + r];
        float4 o;
        o.x = (acc.x + se * bb.x) * sc;
        o.y = (acc.y + se * bb.y) * sc;
        o.z = (acc.z + se * bb.z) * sc;
        o.w = (acc.w + se * bb.w) * sc;
        ((float4*)(g_ye + (size_t)(r0 + r) * D))[lane] = o;
    }
}

// ---------------- out[v] = relu(a_v * sum_{e ∋ v} Ye[e]) ---------------------
// one warp per vertex
__global__ void k_gather(float* __restrict__ out) {
    int w    = (blockIdx.x * blockDim.x + threadIdx.x) >> 5;
    int lane = threadIdx.x & 31;
    if (w >= N_NODES) return;
    int beg = g_rowptr_v[w];
    int end = g_rowptr_v[w + 1];
    float4 acc = make_float4(0.f, 0.f, 0.f, 0.f);
    for (int j = beg; j < end; j++) {
        int e = g_csr_v[j];
        float4 y = __ldg((const float4*)(g_ye + (size_t)e * D) + lane);
        acc.x += y.x; acc.y += y.y; acc.z += y.z; acc.w += y.w;
    }
    float a = g_inv_sqrt_dv[w];
    float4 r;
    r.x = fmaxf(acc.x * a, 0.f);
    r.y = fmaxf(acc.y * a, 0.f);
    r.z = fmaxf(acc.z * a, 0.f);
    r.w = fmaxf(acc.w * a, 0.f);
    ((float4*)(out + (size_t)w * D))[lane] = r;
}

// ---------------- launch -----------------------------------------------------
extern "C" void kernel_launch(void* const* d_in, const int* in_sizes, int n_in,
                              void* d_out, int out_size) {
    const float* X     = (const float*)d_in[0];
    const float* Wm    = (const float*)d_in[1];
    const float* bias  = (const float*)d_in[2];
    const int*   v_idx = (const int*)d_in[3];
    const int*   e_idx = (const int*)d_in[4];
    float*       out   = (float*)d_out;

    k_zero   <<<(N_NODES + 255) / 256, 256>>>();
    k_count  <<<(NNZ_E + 255) / 256, 256>>>(v_idx, e_idx);
    k_scan<N_NODES, true ><<<1, 1024>>>();
    k_scan<N_EDGES, false><<<1, 1024>>>();
    k_scatter<<<(NNZ_E + 255) / 256, 256>>>(v_idx, e_idx);
    k_agg    <<<(N_EDGES * 32 + 255) / 256, 256>>>(X);
    k_gemm   <<<((N_EDGES / 4) * 32 + 255) / 256, 256>>>(Wm, bias);
    k_gather <<<(N_NODES * 32 + 255) / 256, 256>>>(out);
}

// round 2
// speedup vs baseline: 1.3209x; 1.3209x over previous
#include <cuda_runtime.h>

#define N_NODES 100000
#define N_EDGES 20000
#define NNZ_E   1600000
#define D       128
#define NT      (N_NODES + N_EDGES)      // combined count array size
#define SCAN_BE 4096                     // elements per scan block
#define SCAN_NB ((NT + SCAN_BE - 1) / SCAN_BE)   // 30

// ---------------- scratch (static device arrays; no cudaMalloc) --------------
__device__ int   g_cnt[NT];
__device__ int   g_excl[NT];
__device__ int   g_bsum[SCAN_NB];
__device__ int   g_rowptr_v[N_NODES + 1];
__device__ int   g_rowptr_e[N_EDGES + 1];
__device__ int   g_fill_v[N_NODES];
__device__ int   g_fill_e[N_EDGES];
__device__ int   g_csr_v[NNZ_E];    // per-vertex list of incident edges
__device__ int   g_csr_e[NNZ_E];    // per-edge list of incident vertices
__device__ float g_inv_sqrt_dv[N_NODES];
__device__ float g_inv_de[N_EDGES];
__device__ float g_se[N_EDGES];     // s_e = sum of inv_sqrt_dv over edge
__device__ float g_agg[N_EDGES * D];
__device__ float g_ye[N_EDGES * D];

// ---------------- zero + degree counting -------------------------------------
__global__ void k_zero() {
    int i = blockIdx.x * blockDim.x + threadIdx.x;
    if (i < NT) g_cnt[i] = 0;
}

__global__ void k_count(const int* __restrict__ v_idx, const int* __restrict__ e_idx) {
    int i = blockIdx.x * blockDim.x + threadIdx.x;
    if (i < NNZ_E) {
        atomicAdd(&g_cnt[v_idx[i]], 1);
        atomicAdd(&g_cnt[N_NODES + e_idx[i]], 1);
    }
}

// ---------------- 3-phase multi-block exclusive scan --------------------------
// Phase 1: per-block scan (1024 thr x 4 elems), write in-block exclusive + block sum
__global__ void k_scan1() {
    __shared__ int wsum[32];
    const int tid = threadIdx.x, lane = tid & 31, wid = tid >> 5;
    const int base = blockIdx.x * SCAN_BE + tid * 4;

    int4 x = make_int4(0, 0, 0, 0);
    if (base < NT) x = *(const int4*)(g_cnt + base);   // NT % 4 == 0, so all-or-none
    int s = x.x + x.y + x.z + x.w;

    // warp inclusive scan of s
    int v = s;
    #pragma unroll
    for (int o = 1; o < 32; o <<= 1) {
        int t = __shfl_up_sync(0xffffffffu, v, o);
        if (lane >= o) v += t;
    }
    if (lane == 31) wsum[wid] = v;
    __syncthreads();
    if (wid == 0) {
        int w = wsum[lane];
        #pragma unroll
        for (int o = 1; o < 32; o <<= 1) {
            int t = __shfl_up_sync(0xffffffffu, w, o);
            if (lane >= o) w += t;
        }
        wsum[lane] = w;
    }
    __syncthreads();

    int excl = v - s + (wid ? wsum[wid - 1] : 0);   // in-block exclusive for this thread
    if (base < NT) {
        int4 e;
        e.x = excl;
        e.y = e.x + x.x;
        e.z = e.y + x.y;
        e.w = e.z + x.z;
        *(int4*)(g_excl + base) = e;
    }
    if (tid == 0) g_bsum[blockIdx.x] = wsum[31];   // block total
}

// Phase 2: one warp scans the block sums (exclusive, in place)
__global__ void k_scan2() {
    int lane = threadIdx.x;
    int x = (lane < SCAN_NB) ? g_bsum[lane] : 0;
    int v = x;
    #pragma unroll
    for (int o = 1; o < 32; o <<= 1) {
        int t = __shfl_up_sync(0xffffffffu, v, o);
        if (lane >= o) v += t;
    }
    if (lane < SCAN_NB) g_bsum[lane] = v - x;      // exclusive
}

// Phase 3: add block offsets; emit rowptrs, fill cursors, degree scalings
__global__ void k_scan3() {
    int i = blockIdx.x * blockDim.x + threadIdx.x;
    if (i >= NT) return;
    int excl = g_excl[i] + g_bsum[i / SCAN_BE];
    int x    = g_cnt[i];
    if (i < N_NODES) {
        g_rowptr_v[i] = excl;
        g_fill_v[i]   = excl;
        g_inv_sqrt_dv[i] = (x > 0) ? rsqrtf((float)x) : 0.0f;
        if (i == 0) {
            g_rowptr_v[N_NODES] = NNZ_E;   // sum of all vertex degrees
            g_rowptr_e[N_EDGES] = NNZ_E;   // sum of all edge degrees
        }
    } else {
        int e  = i - N_NODES;
        int ex = excl - NNZ_E;             // edge region starts after all v counts
        g_rowptr_e[e] = ex;
        g_fill_e[e]   = ex;
        g_inv_de[e]   = (x > 0) ? (1.0f / (float)x) : 0.0f;
    }
}

// ---------------- CSR fill ---------------------------------------------------
__global__ void k_scatter(const int* __restrict__ v_idx, const int* __restrict__ e_idx) {
    int i = blockIdx.x * blockDim.x + threadIdx.x;
    if (i < NNZ_E) {
        int v = v_idx[i];
        int e = e_idx[i];
        int pe = atomicAdd(&g_fill_e[e], 1);
        g_csr_e[pe] = v;
        int pv = atomicAdd(&g_fill_v[v], 1);
        g_csr_v[pv] = e;
    }
}

// ---------------- Agg[e] = sum_{v in e} a_v * X[v];  s_e = sum a_v -----------
// one warp per hyperedge; lane owns 4 consecutive columns (float4)
__global__ void k_agg(const float* __restrict__ X) {
    int w    = (blockIdx.x * blockDim.x + threadIdx.x) >> 5;
    int lane = threadIdx.x & 31;
    if (w >= N_EDGES) return;
    int beg = g_rowptr_e[w];
    int end = g_rowptr_e[w + 1];
    float4 acc = make_float4(0.f, 0.f, 0.f, 0.f);
    float  s   = 0.f;
    for (int j = beg; j < end; j++) {
        int   v = g_csr_e[j];
        float a = g_inv_sqrt_dv[v];
        float4 x = __ldg((const float4*)(X + (size_t)v * D) + lane);
        acc.x += a * x.x; acc.y += a * x.y; acc.z += a * x.z; acc.w += a * x.w;
        s += a;
    }
    ((float4*)(g_agg + (size_t)w * D))[lane] = acc;
    if (lane == 0) g_se[w] = s;
}

// ---------------- Ye = (Agg @ W + s_e * b) * inv_de --------------------------
// one warp per 4 edge-rows; lane owns 4 output cols; W rows read via L1
__global__ void k_gemm(const float* __restrict__ Wm, const float* __restrict__ bias) {
    int w    = (blockIdx.x * blockDim.x + threadIdx.x) >> 5;
    int lane = threadIdx.x & 31;
    int r0   = w * 4;
    if (r0 >= N_EDGES) return;

    float4 acc0 = make_float4(0.f, 0.f, 0.f, 0.f);
    float4 acc1 = acc0, acc2 = acc0, acc3 = acc0;
    const float* A = g_agg + (size_t)r0 * D;

    #pragma unroll 4
    for (int k = 0; k < D; k++) {
        float4 wk = __ldg((const float4*)(Wm + (size_t)k * D) + lane);
        float a0 = __ldg(A + k);
        float a1 = __ldg(A + D + k);
        float a2 = __ldg(A + 2 * D + k);
        float a3 = __ldg(A + 3 * D + k);
        acc0.x += a0 * wk.x; acc0.y += a0 * wk.y; acc0.z += a0 * wk.z; acc0.w += a0 * wk.w;
        acc1.x += a1 * wk.x; acc1.y += a1 * wk.y; acc1.z += a1 * wk.z; acc1.w += a1 * wk.w;
        acc2.x += a2 * wk.x; acc2.y += a2 * wk.y; acc2.z += a2 * wk.z; acc2.w += a2 * wk.w;
        acc3.x += a3 * wk.x; acc3.y += a3 * wk.y; acc3.z += a3 * wk.z; acc3.w += a3 * wk.w;
    }

    float4 bb = __ldg((const float4*)bias + lane);
    #pragma unroll
    for (int r = 0; r < 4; r++) {
        float4 acc = (r == 0) ? acc0 : (r == 1) ? acc1 : (r == 2) ? acc2 : acc3;
        float se  = g_se[r0 + r];
        float sc  = g_inv_de[r0 + r];
        float4 o;
        o.x = (acc.x + se * bb.x) * sc;
        o.y = (acc.y + se * bb.y) * sc;
        o.z = (acc.z + se * bb.z) * sc;
        o.w = (acc.w + se * bb.w) * sc;
        ((float4*)(g_ye + (size_t)(r0 + r) * D))[lane] = o;
    }
}

// ---------------- out[v] = relu(a_v * sum_{e ∋ v} Ye[e]) ---------------------
// one warp per vertex
__global__ void k_gather(float* __restrict__ out) {
    int w    = (blockIdx.x * blockDim.x + threadIdx.x) >> 5;
    int lane = threadIdx.x & 31;
    if (w >= N_NODES) return;
    int beg = g_rowptr_v[w];
    int end = g_rowptr_v[w + 1];
    float4 acc = make_float4(0.f, 0.f, 0.f, 0.f);
    for (int j = beg; j < end; j++) {
        int e = g_csr_v[j];
        float4 y = __ldg((const float4*)(g_ye + (size_t)e * D) + lane);
        acc.x += y.x; acc.y += y.y; acc.z += y.z; acc.w += y.w;
    }
    float a = g_inv_sqrt_dv[w];
    float4 r;
    r.x = fmaxf(acc.x * a, 0.f);
    r.y = fmaxf(acc.y * a, 0.f);
    r.z = fmaxf(acc.z * a, 0.f);
    r.w = fmaxf(acc.w * a, 0.f);
    ((float4*)(out + (size_t)w * D))[lane] = r;
}

// ---------------- launch -----------------------------------------------------
extern "C" void kernel_launch(void* const* d_in, const int* in_sizes, int n_in,
                              void* d_out, int out_size) {
    const float* X     = (const float*)d_in[0];
    const float* Wm    = (const float*)d_in[1];
    const float* bias  = (const float*)d_in[2];
    const int*   v_idx = (const int*)d_in[3];
    const int*   e_idx = (const int*)d_in[4];
    float*       out   = (float*)d_out;

    k_zero   <<<(NT + 255) / 256, 256>>>();
    k_count  <<<(NNZ_E + 255) / 256, 256>>>(v_idx, e_idx);
    k_scan1  <<<SCAN_NB, 1024>>>();
    k_scan2  <<<1, 32>>>();
    k_scan3  <<<(NT + 255) / 256, 256>>>();
    k_scatter<<<(NNZ_E + 255) / 256, 256>>>(v_idx, e_idx);
    k_agg    <<<(N_EDGES * 32 + 255) / 256, 256>>>(X);
    k_gemm   <<<((N_EDGES / 4) * 32 + 255) / 256, 256>>>(Wm, bias);
    k_gather <<<(N_NODES * 32 + 255) / 256, 256>>>(out);
}

// round 3
// speedup vs baseline: 1.3776x; 1.0430x over previous
#include <cuda_runtime.h>

#define N_NODES 100000
#define N_EDGES 20000
#define NNZ_E   1600000
#define D       128
#define NT      (N_NODES + N_EDGES)      // combined count array size
#define SCAN_BE 4096                     // elements per scan block
#define SCAN_NB ((NT + SCAN_BE - 1) / SCAN_BE)   // 30

// ---------------- scratch (static device arrays; no cudaMalloc) --------------
__device__ __align__(16) int   g_cnt[NT];
__device__ __align__(16) int   g_excl[NT];
__device__ int   g_bsum[32];
__device__ int   g_rowptr_v[N_NODES + 1];
__device__ int   g_rowptr_e[N_EDGES + 1];
__device__ int   g_fill_v[N_NODES];
__device__ int   g_fill_e[N_EDGES];
__device__ int   g_csr_v[NNZ_E];    // per-vertex list of incident edges
__device__ int   g_csr_e[NNZ_E];    // per-edge list of incident vertices
__device__ float g_inv_sqrt_dv[N_NODES];
__device__ float g_inv_de[N_EDGES];
__device__ float g_se[N_EDGES];     // s_e = sum of inv_sqrt_dv over edge
__device__ __align__(16) float g_agg[N_EDGES * D];
__device__ __align__(16) float g_ye[N_EDGES * D];

// ---------------- degree counting (int4-vectorized) ---------------------------
__global__ void k_count(const int* __restrict__ v_idx, const int* __restrict__ e_idx) {
    int t = blockIdx.x * blockDim.x + threadIdx.x;
    int i = t * 4;
    if (i < NNZ_E) {                               // NNZ_E % 4 == 0
        int4 v = __ldg((const int4*)(v_idx + i));
        int4 e = __ldg((const int4*)(e_idx + i));
        atomicAdd(&g_cnt[v.x], 1); atomicAdd(&g_cnt[v.y], 1);
        atomicAdd(&g_cnt[v.z], 1); atomicAdd(&g_cnt[v.w], 1);
        atomicAdd(&g_cnt[N_NODES + e.x], 1); atomicAdd(&g_cnt[N_NODES + e.y], 1);
        atomicAdd(&g_cnt[N_NODES + e.z], 1); atomicAdd(&g_cnt[N_NODES + e.w], 1);
    }
}

// ---------------- scan phase 1: per-block exclusive + block sums ---------------
__global__ void k_scan1() {
    __shared__ int wsum[32];
    const int tid = threadIdx.x, lane = tid & 31, wid = tid >> 5;
    const int base = blockIdx.x * SCAN_BE + tid * 4;

    int4 x = make_int4(0, 0, 0, 0);
    if (base < NT) x = *(const int4*)(g_cnt + base);   // NT % 4 == 0 -> all-or-none
    int s = x.x + x.y + x.z + x.w;

    int v = s;
    #pragma unroll
    for (int o = 1; o < 32; o <<= 1) {
        int t = __shfl_up_sync(0xffffffffu, v, o);
        if (lane >= o) v += t;
    }
    if (lane == 31) wsum[wid] = v;
    __syncthreads();
    if (wid == 0) {
        int w = wsum[lane];
        #pragma unroll
        for (int o = 1; o < 32; o <<= 1) {
            int t = __shfl_up_sync(0xffffffffu, w, o);
            if (lane >= o) w += t;
        }
        wsum[lane] = w;
    }
    __syncthreads();

    int excl = v - s + (wid ? wsum[wid - 1] : 0);
    if (base < NT) {
        int4 e;
        e.x = excl;
        e.y = e.x + x.x;
        e.z = e.y + x.y;
        e.w = e.z + x.z;
        *(int4*)(g_excl + base) = e;
    }
    if (tid == 0) g_bsum[blockIdx.x] = wsum[31];
}

// ---------------- scan phase 2 (fused): add offsets, emit metadata -------------
__global__ void k_scan3() {
    __shared__ int boff[SCAN_NB];
    const int tid = threadIdx.x;
    if (tid < 32) {                          // warp 0 scans the 30 block sums
        int x = (tid < SCAN_NB) ? g_bsum[tid] : 0;
        int v = x;
        #pragma unroll
        for (int o = 1; o < 32; o <<= 1) {
            int t = __shfl_up_sync(0xffffffffu, v, o);
            if (tid >= o) v += t;
        }
        if (tid < SCAN_NB) boff[tid] = v - x;   // exclusive
    }
    __syncthreads();

    int i = blockIdx.x * blockDim.x + tid;
    if (i >= NT) return;
    int excl = g_excl[i] + boff[i / SCAN_BE];
    int x    = g_cnt[i];
    if (i < N_NODES) {
        g_rowptr_v[i] = excl;
        g_fill_v[i]   = excl;
        g_inv_sqrt_dv[i] = (x > 0) ? rsqrtf((float)x) : 0.0f;
        if (i == 0) {
            g_rowptr_v[N_NODES] = NNZ_E;
            g_rowptr_e[N_EDGES] = NNZ_E;
        }
    } else {
        int e  = i - N_NODES;
        int ex = excl - NNZ_E;               // edge region starts after all v counts
        g_rowptr_e[e] = ex;
        g_fill_e[e]   = ex;
        g_inv_de[e]   = (x > 0) ? (1.0f / (float)x) : 0.0f;
    }
}

// ---------------- CSR fill (int4-vectorized) ----------------------------------
__global__ void k_scatter(const int* __restrict__ v_idx, const int* __restrict__ e_idx) {
    int t = blockIdx.x * blockDim.x + threadIdx.x;
    int i = t * 4;
    if (i < NNZ_E) {
        int4 v = __ldg((const int4*)(v_idx + i));
        int4 e = __ldg((const int4*)(e_idx + i));
        int p;
        p = atomicAdd(&g_fill_e[e.x], 1); g_csr_e[p] = v.x;
        p = atomicAdd(&g_fill_e[e.y], 1); g_csr_e[p] = v.y;
        p = atomicAdd(&g_fill_e[e.z], 1); g_csr_e[p] = v.z;
        p = atomicAdd(&g_fill_e[e.w], 1); g_csr_e[p] = v.w;
        p = atomicAdd(&g_fill_v[v.x], 1); g_csr_v[p] = e.x;
        p = atomicAdd(&g_fill_v[v.y], 1); g_csr_v[p] = e.y;
        p = atomicAdd(&g_fill_v[v.z], 1); g_csr_v[p] = e.z;
        p = atomicAdd(&g_fill_v[v.w], 1); g_csr_v[p] = e.w;
    }
}

// ---------------- Agg[e] = sum_{v in e} a_v * X[v];  s_e = sum a_v ------------
// one warp per hyperedge; lane owns 4 consecutive columns; unroll-by-4 for MLP
__global__ __launch_bounds__(256) void k_agg(const float* __restrict__ X) {
    int w    = (blockIdx.x * blockDim.x + threadIdx.x) >> 5;
    int lane = threadIdx.x & 31;
    if (w >= N_EDGES) return;
    int beg = g_rowptr_e[w];
    int end = g_rowptr_e[w + 1];
    float4 acc = make_float4(0.f, 0.f, 0.f, 0.f);
    float  s   = 0.f;
    int j = beg;
    for (; j + 4 <= end; j += 4) {
        int v0 = __ldg(g_csr_e + j    );
        int v1 = __ldg(g_csr_e + j + 1);
        int v2 = __ldg(g_csr_e + j + 2);
        int v3 = __ldg(g_csr_e + j + 3);
        float a0 = __ldg(g_inv_sqrt_dv + v0);
        float a1 = __ldg(g_inv_sqrt_dv + v1);
        float a2 = __ldg(g_inv_sqrt_dv + v2);
        float a3 = __ldg(g_inv_sqrt_dv + v3);
        float4 x0 = __ldg((const float4*)(X + (size_t)v0 * D) + lane);
        float4 x1 = __ldg((const float4*)(X + (size_t)v1 * D) + lane);
        float4 x2 = __ldg((const float4*)(X + (size_t)v2 * D) + lane);
        float4 x3 = __ldg((const float4*)(X + (size_t)v3 * D) + lane);
        acc.x += a0 * x0.x; acc.y += a0 * x0.y; acc.z += a0 * x0.z; acc.w += a0 * x0.w;
        acc.x += a1 * x1.x; acc.y += a1 * x1.y; acc.z += a1 * x1.z; acc.w += a1 * x1.w;
        acc.x += a2 * x2.x; acc.y += a2 * x2.y; acc.z += a2 * x2.z; acc.w += a2 * x2.w;
        acc.x += a3 * x3.x; acc.y += a3 * x3.y; acc.z += a3 * x3.z; acc.w += a3 * x3.w;
        s += a0 + a1 + a2 + a3;
    }
    for (; j < end; j++) {
        int   v = __ldg(g_csr_e + j);
        float a = __ldg(g_inv_sqrt_dv + v);
        float4 x = __ldg((const float4*)(X + (size_t)v * D) + lane);
        acc.x += a * x.x; acc.y += a * x.y; acc.z += a * x.z; acc.w += a * x.w;
        s += a;
    }
    ((float4*)(g_agg + (size_t)w * D))[lane] = acc;
    if (lane == 0) g_se[w] = s;
}

// ---------------- Ye = (Agg @ W + s_e * b) * inv_de ---------------------------
__global__ __launch_bounds__(256) void k_gemm(const float* __restrict__ Wm, const float* __restrict__ bias) {
    int w    = (blockIdx.x * blockDim.x + threadIdx.x) >> 5;
    int lane = threadIdx.x & 31;
    int r0   = w * 4;
    if (r0 >= N_EDGES) return;

    float4 acc0 = make_float4(0.f, 0.f, 0.f, 0.f);
    float4 acc1 = acc0, acc2 = acc0, acc3 = acc0;
    const float* A = g_agg + (size_t)r0 * D;

    #pragma unroll 4
    for (int k = 0; k < D; k++) {
        float4 wk = __ldg((const float4*)(Wm + (size_t)k * D) + lane);
        float a0 = __ldg(A + k);
        float a1 = __ldg(A + D + k);
        float a2 = __ldg(A + 2 * D + k);
        float a3 = __ldg(A + 3 * D + k);
        acc0.x += a0 * wk.x; acc0.y += a0 * wk.y; acc0.z += a0 * wk.z; acc0.w += a0 * wk.w;
        acc1.x += a1 * wk.x; acc1.y += a1 * wk.y; acc1.z += a1 * wk.z; acc1.w += a1 * wk.w;
        acc2.x += a2 * wk.x; acc2.y += a2 * wk.y; acc2.z += a2 * wk.z; acc2.w += a2 * wk.w;
        acc3.x += a3 * wk.x; acc3.y += a3 * wk.y; acc3.z += a3 * wk.z; acc3.w += a3 * wk.w;
    }

    float4 bb = __ldg((const float4*)bias + lane);
    #pragma unroll
    for (int r = 0; r < 4; r++) {
        float4 acc = (r == 0) ? acc0 : (r == 1) ? acc1 : (r == 2) ? acc2 : acc3;
        float se  = g_se[r0 + r];
        float sc  = g_inv_de[r0 + r];
        float4 o;
        o.x = (acc.x + se * bb.x) * sc;
        o.y = (acc.y + se * bb.y) * sc;
        o.z = (acc.z + se * bb.z) * sc;
        o.w = (acc.w + se * bb.w) * sc;
        ((float4*)(g_ye + (size_t)(r0 + r) * D))[lane] = o;
    }
}

// ---------------- out[v] = relu(a_v * sum_{e in v} Ye[e]) ---------------------
__global__ __launch_bounds__(256) void k_gather(float* __restrict__ out) {
    int w    = (blockIdx.x * blockDim.x + threadIdx.x) >> 5;
    int lane = threadIdx.x & 31;
    if (w >= N_NODES) return;
    int beg = g_rowptr_v[w];
    int end = g_rowptr_v[w + 1];
    float4 acc = make_float4(0.f, 0.f, 0.f, 0.f);
    int j = beg;
    for (; j + 4 <= end; j += 4) {
        int e0 = __ldg(g_csr_v + j    );
        int e1 = __ldg(g_csr_v + j + 1);
        int e2 = __ldg(g_csr_v + j + 2);
        int e3 = __ldg(g_csr_v + j + 3);
        float4 y0 = __ldg((const float4*)(g_ye + (size_t)e0 * D) + lane);
        float4 y1 = __ldg((const float4*)(g_ye + (size_t)e1 * D) + lane);
        float4 y2 = __ldg((const float4*)(g_ye + (size_t)e2 * D) + lane);
        float4 y3 = __ldg((const float4*)(g_ye + (size_t)e3 * D) + lane);
        acc.x += y0.x + y1.x + y2.x + y3.x;
        acc.y += y0.y + y1.y + y2.y + y3.y;
        acc.z += y0.z + y1.z + y2.z + y3.z;
        acc.w += y0.w + y1.w + y2.w + y3.w;
    }
    for (; j < end; j++) {
        int e = __ldg(g_csr_v + j);
        float4 y = __ldg((const float4*)(g_ye + (size_t)e * D) + lane);
        acc.x += y.x; acc.y += y.y; acc.z += y.z; acc.w += y.w;
    }
    float a = g_inv_sqrt_dv[w];
    float4 r;
    r.x = fmaxf(acc.x * a, 0.f);
    r.y = fmaxf(acc.y * a, 0.f);
    r.z = fmaxf(acc.z * a, 0.f);
    r.w = fmaxf(acc.w * a, 0.f);
    ((float4*)(out + (size_t)w * D))[lane] = r;
}

// ---------------- launch -----------------------------------------------------
extern "C" void kernel_launch(void* const* d_in, const int* in_sizes, int n_in,
                              void* d_out, int out_size) {
    const float* X     = (const float*)d_in[0];
    const float* Wm    = (const float*)d_in[1];
    const float* bias  = (const float*)d_in[2];
    const int*   v_idx = (const int*)d_in[3];
    const int*   e_idx = (const int*)d_in[4];
    float*       out   = (float*)d_out;

    void* cnt_ptr = nullptr;
    cudaGetSymbolAddress(&cnt_ptr, g_cnt);
    cudaMemsetAsync(cnt_ptr, 0, NT * sizeof(int));

    k_count  <<<(NNZ_E / 4 + 255) / 256, 256>>>(v_idx, e_idx);
    k_scan1  <<<SCAN_NB, 1024>>>();
    k_scan3  <<<(NT + 255) / 256, 256>>>();
    k_scatter<<<(NNZ_E / 4 + 255) / 256, 256>>>(v_idx, e_idx);
    k_agg    <<<(N_EDGES * 32 + 255) / 256, 256>>>(X);
    k_gemm   <<<((N_EDGES / 4) * 32 + 255) / 256, 256>>>(Wm, bias);
    k_gather <<<(N_NODES * 32 + 255) / 256, 256>>>(out);
}

// round 5
// speedup vs baseline: 1.4974x; 1.0870x over previous
#include <cuda_runtime.h>
#include <cuda_fp16.h>

#define N_NODES 100000
#define N_EDGES 20000
#define NNZ_E   1600000
#define D       128
#define NT      (N_NODES + N_EDGES)      // combined count array size
#define SCAN_BE 4096                     // elements per scan block
#define SCAN_NB ((NT + SCAN_BE - 1) / SCAN_BE)   // 30

// ---------------- scratch (static device arrays; no cudaMalloc) --------------
__device__ __align__(16) int   g_cnt[NT];
__device__ __align__(16) int   g_excl[NT];
__device__ int   g_bsum[32];
__device__ int   g_rowptr_v[N_NODES + 1];
__device__ int   g_rowptr_e[N_EDGES + 1];
__device__ __align__(16) int g_rank[NNZ_E];   // packed: rank_v | rank_e<<16
__device__ int   g_csr_v[NNZ_E];    // per-vertex list of incident edges
__device__ int   g_csr_e[NNZ_E];    // per-edge list of incident vertices
__device__ float g_inv_sqrt_dv[N_NODES];
__device__ float g_inv_de[N_EDGES];
__device__ float g_se[N_EDGES];     // s_e = sum of inv_sqrt_dv over edge
__device__ __align__(16) float  g_agg[N_EDGES * D];
__device__ __align__(16) __half g_xh[(size_t)N_NODES * D];   // fp16-staged X
__device__ __align__(16) __half g_yeh[(size_t)N_EDGES * D];  // fp16-staged Ye

// ---------------- X -> fp16 staging ------------------------------------------
__global__ void k_cvt(const float* __restrict__ X) {
    int i = blockIdx.x * blockDim.x + threadIdx.x;      // over N*D/4
    if (i < N_NODES * D / 4) {
        float4 x = __ldg((const float4*)X + i);
        __half2 h0 = __floats2half2_rn(x.x, x.y);
        __half2 h1 = __floats2half2_rn(x.z, x.w);
        uint2 p = make_uint2(*reinterpret_cast<unsigned*>(&h0),
                             *reinterpret_cast<unsigned*>(&h1));
        ((uint2*)g_xh)[i] = p;
    }
}

// ---------------- degree counting + rank recording ----------------------------
__global__ void k_count(const int* __restrict__ v_idx, const int* __restrict__ e_idx) {
    int t = blockIdx.x * blockDim.x + threadIdx.x;
    int i = t * 4;
    if (i < NNZ_E) {                               // NNZ_E % 4 == 0
        int4 v = __ldg((const int4*)(v_idx + i));
        int4 e = __ldg((const int4*)(e_idx + i));
        int rv0 = atomicAdd(&g_cnt[v.x], 1);
        int rv1 = atomicAdd(&g_cnt[v.y], 1);
        int rv2 = atomicAdd(&g_cnt[v.z], 1);
        int rv3 = atomicAdd(&g_cnt[v.w], 1);
        int re0 = atomicAdd(&g_cnt[N_NODES + e.x], 1);
        int re1 = atomicAdd(&g_cnt[N_NODES + e.y], 1);
        int re2 = atomicAdd(&g_cnt[N_NODES + e.z], 1);
        int re3 = atomicAdd(&g_cnt[N_NODES + e.w], 1);
        int4 r;
        r.x = rv0 | (re0 << 16);
        r.y = rv1 | (re1 << 16);
        r.z = rv2 | (re2 << 16);
        r.w = rv3 | (re3 << 16);
        *(int4*)(g_rank + i) = r;
    }
}

// ---------------- scan phase 1: per-block exclusive + block sums ---------------
__global__ void k_scan1() {
    __shared__ int wsum[32];
    const int tid = threadIdx.x, lane = tid & 31, wid = tid >> 5;
    const int base = blockIdx.x * SCAN_BE + tid * 4;

    int4 x = make_int4(0, 0, 0, 0);
    if (base < NT) x = *(const int4*)(g_cnt + base);   // NT % 4 == 0 -> all-or-none
    int s = x.x + x.y + x.z + x.w;

    int v = s;
    #pragma unroll
    for (int o = 1; o < 32; o <<= 1) {
        int t = __shfl_up_sync(0xffffffffu, v, o);
        if (lane >= o) v += t;
    }
    if (lane == 31) wsum[wid] = v;
    __syncthreads();
    if (wid == 0) {
        int w = wsum[lane];
        #pragma unroll
        for (int o = 1; o < 32; o <<= 1) {
            int t = __shfl_up_sync(0xffffffffu, w, o);
            if (lane >= o) w += t;
        }
        wsum[lane] = w;
    }
    __syncthreads();

    int excl = v - s + (wid ? wsum[wid - 1] : 0);
    if (base < NT) {
        int4 e;
        e.x = excl;
        e.y = e.x + x.x;
        e.z = e.y + x.y;
        e.w = e.z + x.z;
        *(int4*)(g_excl + base) = e;
    }
    if (tid == 0) g_bsum[blockIdx.x] = wsum[31];
}

// ---------------- scan phase 2 (fused): add offsets, emit metadata -------------
__global__ void k_scan3() {
    __shared__ int boff[SCAN_NB];
    const int tid = threadIdx.x;
    if (tid < 32) {                          // warp 0 scans the 30 block sums
        int x = (tid < SCAN_NB) ? g_bsum[tid] : 0;
        int v = x;
        #pragma unroll
        for (int o = 1; o < 32; o <<= 1) {
            int t = __shfl_up_sync(0xffffffffu, v, o);
            if (tid >= o) v += t;
        }
        if (tid < SCAN_NB) boff[tid] = v - x;   // exclusive
    }
    __syncthreads();

    int i = blockIdx.x * blockDim.x + tid;
    if (i >= NT) return;
    int excl = g_excl[i] + boff[i / SCAN_BE];
    int x    = g_cnt[i];
    if (i < N_NODES) {
        g_rowptr_v[i] = excl;
        g_inv_sqrt_dv[i] = (x > 0) ? rsqrtf((float)x) : 0.0f;
        if (i == 0) {
            g_rowptr_v[N_NODES] = NNZ_E;
            g_rowptr_e[N_EDGES] = NNZ_E;
        }
    } else {
        int e  = i - N_NODES;
        g_rowptr_e[e] = excl - NNZ_E;        // edge region starts after all v counts
        g_inv_de[e]   = (x > 0) ? (1.0f / (float)x) : 0.0f;
    }
}

// ---------------- CSR fill: atomic-free via recorded ranks ---------------------
__global__ void k_scatter(const int* __restrict__ v_idx, const int* __restrict__ e_idx) {
    int t = blockIdx.x * blockDim.x + threadIdx.x;
    int i = t * 4;
    if (i < NNZ_E) {
        int4 v = __ldg((const int4*)(v_idx + i));
        int4 e = __ldg((const int4*)(e_idx + i));
        int4 r = *(const int4*)(g_rank + i);
        g_csr_v[__ldg(g_rowptr_v + v.x) + (r.x & 0xffff)] = e.x;
        g_csr_v[__ldg(g_rowptr_v + v.y) + (r.y & 0xffff)] = e.y;
        g_csr_v[__ldg(g_rowptr_v + v.z) + (r.z & 0xffff)] = e.z;
        g_csr_v[__ldg(g_rowptr_v + v.w) + (r.w & 0xffff)] = e.w;
        g_csr_e[__ldg(g_rowptr_e + e.x) + (r.x >> 16)] = v.x;
        g_csr_e[__ldg(g_rowptr_e + e.y) + (r.y >> 16)] = v.y;
        g_csr_e[__ldg(g_rowptr_e + e.z) + (r.z >> 16)] = v.z;
        g_csr_e[__ldg(g_rowptr_e + e.w) + (r.w >> 16)] = v.w;
    }
}

// ---------------- Agg[e] = sum_{v in e} a_v * X[v];  s_e = sum a_v ------------
// one warp per hyperedge; lane owns 4 cols (fp16 loads, fp32 accumulate)
__global__ __launch_bounds__(256) void k_agg() {
    int w    = (blockIdx.x * blockDim.x + threadIdx.x) >> 5;
    int lane = threadIdx.x & 31;
    if (w >= N_EDGES) return;
    int beg = g_rowptr_e[w];
    int end = g_rowptr_e[w + 1];
    float4 acc = make_float4(0.f, 0.f, 0.f, 0.f);
    float  s   = 0.f;
    int j = beg;
    for (; j + 4 <= end; j += 4) {
        int v0 = __ldg(g_csr_e + j    );
        int v1 = __ldg(g_csr_e + j + 1);
        int v2 = __ldg(g_csr_e + j + 2);
        int v3 = __ldg(g_csr_e + j + 3);
        float a0 = __ldg(g_inv_sqrt_dv + v0);
        float a1 = __ldg(g_inv_sqrt_dv + v1);
        float a2 = __ldg(g_inv_sqrt_dv + v2);
        float a3 = __ldg(g_inv_sqrt_dv + v3);
        uint2 u0 = __ldg((const uint2*)(g_xh + (size_t)v0 * D) + lane);
        uint2 u1 = __ldg((const uint2*)(g_xh + (size_t)v1 * D) + lane);
        uint2 u2 = __ldg((const uint2*)(g_xh + (size_t)v2 * D) + lane);
        uint2 u3 = __ldg((const uint2*)(g_xh + (size_t)v3 * D) + lane);
        float2 f;
        f = __half22float2(*reinterpret_cast<__half2*>(&u0.x)); acc.x += a0*f.x; acc.y += a0*f.y;
        f = __half22float2(*reinterpret_cast<__half2*>(&u0.y)); acc.z += a0*f.x; acc.w += a0*f.y;
        f = __half22float2(*reinterpret_cast<__half2*>(&u1.x)); acc.x += a1*f.x; acc.y += a1*f.y;
        f = __half22float2(*reinterpret_cast<__half2*>(&u1.y)); acc.z += a1*f.x; acc.w += a1*f.y;
        f = __half22float2(*reinterpret_cast<__half2*>(&u2.x)); acc.x += a2*f.x; acc.y += a2*f.y;
        f = __half22float2(*reinterpret_cast<__half2*>(&u2.y)); acc.z += a2*f.x; acc.w += a2*f.y;
        f = __half22float2(*reinterpret_cast<__half2*>(&u3.x)); acc.x += a3*f.x; acc.y += a3*f.y;
        f = __half22float2(*reinterpret_cast<__half2*>(&u3.y)); acc.z += a3*f.x; acc.w += a3*f.y;
        s += a0 + a1 + a2 + a3;
    }
    for (; j < end; j++) {
        int   v = __ldg(g_csr_e + j);
        float a = __ldg(g_inv_sqrt_dv + v);
        uint2 u = __ldg((const uint2*)(g_xh + (size_t)v * D) + lane);
        float2 f;
        f = __half22float2(*reinterpret_cast<__half2*>(&u.x)); acc.x += a*f.x; acc.y += a*f.y;
        f = __half22float2(*reinterpret_cast<__half2*>(&u.y)); acc.z += a*f.x; acc.w += a*f.y;
        s += a;
    }
    ((float4*)(g_agg + (size_t)w * D))[lane] = acc;
    if (lane == 0) g_se[w] = s;
}

// ---------------- Ye = (Agg @ W + s_e * b) * inv_de  (fp16 output) ------------
__global__ __launch_bounds__(256) void k_gemm(const float* __restrict__ Wm, const float* __restrict__ bias) {
    int w    = (blockIdx.x * blockDim.x + threadIdx.x) >> 5;
    int lane = threadIdx.x & 31;
    int r0   = w * 4;
    if (r0 >= N_EDGES) return;

    float4 acc0 = make_float4(0.f, 0.f, 0.f, 0.f);
    float4 acc1 = acc0, acc2 = acc0, acc3 = acc0;
    const float* A = g_agg + (size_t)r0 * D;

    #pragma unroll 4
    for (int k = 0; k < D; k++) {
        float4 wk = __ldg((const float4*)(Wm + (size_t)k * D) + lane);
        float a0 = __ldg(A + k);
        float a1 = __ldg(A + D + k);
        float a2 = __ldg(A + 2 * D + k);
        float a3 = __ldg(A + 3 * D + k);
        acc0.x += a0 * wk.x; acc0.y += a0 * wk.y; acc0.z += a0 * wk.z; acc0.w += a0 * wk.w;
        acc1.x += a1 * wk.x; acc1.y += a1 * wk.y; acc1.z += a1 * wk.z; acc1.w += a1 * wk.w;
        acc2.x += a2 * wk.x; acc2.y += a2 * wk.y; acc2.z += a2 * wk.z; acc2.w += a2 * wk.w;
        acc3.x += a3 * wk.x; acc3.y += a3 * wk.y; acc3.z += a3 * wk.z; acc3.w += a3 * wk.w;
    }

    float4 bb = __ldg((const float4*)bias + lane);
    #pragma unroll
    for (int r = 0; r < 4; r++) {
        float4 acc = (r == 0) ? acc0 : (r == 1) ? acc1 : (r == 2) ? acc2 : acc3;
        float se  = g_se[r0 + r];
        float sc  = g_inv_de[r0 + r];
        __half2 h0 = __floats2half2_rn((acc.x + se * bb.x) * sc,
                                       (acc.y + se * bb.y) * sc);
        __half2 h1 = __floats2half2_rn((acc.z + se * bb.z) * sc,
                                       (acc.w + se * bb.w) * sc);
        uint2 p = make_uint2(*reinterpret_cast<unsigned*>(&h0),
                             *reinterpret_cast<unsigned*>(&h1));
        ((uint2*)(g_yeh + (size_t)(r0 + r) * D))[lane] = p;
    }
}

// ---------------- out[v] = relu(a_v * sum_{e in v} Ye[e]) ---------------------
__global__ __launch_bounds__(256) void k_gather(float* __restrict__ out) {
    int w    = (blockIdx.x * blockDim.x + threadIdx.x) >> 5;
    int lane = threadIdx.x & 31;
    if (w >= N_NODES) return;
    int beg = g_rowptr_v[w];
    int end = g_rowptr_v[w + 1];
    float4 acc = make_float4(0.f, 0.f, 0.f, 0.f);
    int j = beg;
    for (; j + 4 <= end; j += 4) {
        int e0 = __ldg(g_csr_v + j    );
        int e1 = __ldg(g_csr_v + j + 1);
        int e2 = __ldg(g_csr_v + j + 2);
        int e3 = __ldg(g_csr_v + j + 3);
        uint2 u0 = __ldg((const uint2*)(g_yeh + (size_t)e0 * D) + lane);
        uint2 u1 = __ldg((const uint2*)(g_yeh + (size_t)e1 * D) + lane);
        uint2 u2 = __ldg((const uint2*)(g_yeh + (size_t)e2 * D) + lane);
        uint2 u3 = __ldg((const uint2*)(g_yeh + (size_t)e3 * D) + lane);
        float2 f;
        f = __half22float2(*reinterpret_cast<__half2*>(&u0.x)); acc.x += f.x; acc.y += f.y;
        f = __half22float2(*reinterpret_cast<__half2*>(&u0.y)); acc.z += f.x; acc.w += f.y;
        f = __half22float2(*reinterpret_cast<__half2*>(&u1.x)); acc.x += f.x; acc.y += f.y;
        f = __half22float2(*reinterpret_cast<__half2*>(&u1.y)); acc.z += f.x; acc.w += f.y;
        f = __half22float2(*reinterpret_cast<__half2*>(&u2.x)); acc.x += f.x; acc.y += f.y;
        f = __half22float2(*reinterpret_cast<__half2*>(&u2.y)); acc.z += f.x; acc.w += f.y;
        f = __half22float2(*reinterpret_cast<__half2*>(&u3.x)); acc.x += f.x; acc.y += f.y;
        f = __half22float2(*reinterpret_cast<__half2*>(&u3.y)); acc.z += f.x; acc.w += f.y;
    }
    for (; j < end; j++) {
        int e = __ldg(g_csr_v + j);
        uint2 u = __ldg((const uint2*)(g_yeh + (size_t)e * D) + lane);
        float2 f;
        f = __half22float2(*reinterpret_cast<__half2*>(&u.x)); acc.x += f.x; acc.y += f.y;
        f = __half22float2(*reinterpret_cast<__half2*>(&u.y)); acc.z += f.x; acc.w += f.y;
    }
    float a = g_inv_sqrt_dv[w];
    float4 r;
    r.x = fmaxf(acc.x * a, 0.f);
    r.y = fmaxf(acc.y * a, 0.f);
    r.z = fmaxf(acc.z * a, 0.f);
    r.w = fmaxf(acc.w * a, 0.f);
    ((float4*)(out + (size_t)w * D))[lane] = r;
}

// ---------------- launch -----------------------------------------------------
extern "C" void kernel_launch(void* const* d_in, const int* in_sizes, int n_in,
                              void* d_out, int out_size) {
    const float* X     = (const float*)d_in[0];
    const float* Wm    = (const float*)d_in[1];
    const float* bias  = (const float*)d_in[2];
    const int*   v_idx = (const int*)d_in[3];
    const int*   e_idx = (const int*)d_in[4];
    float*       out   = (float*)d_out;

    void* cnt_ptr = nullptr;
    cudaGetSymbolAddress(&cnt_ptr, g_cnt);
    cudaMemsetAsync(cnt_ptr, 0, NT * sizeof(int));

    k_cvt    <<<(N_NODES * D / 4 + 255) / 256, 256>>>(X);
    k_count  <<<(NNZ_E / 4 + 255) / 256, 256>>>(v_idx, e_idx);
    k_scan1  <<<SCAN_NB, 1024>>>();
    k_scan3  <<<(NT + 255) / 256, 256>>>();
    k_scatter<<<(NNZ_E / 4 + 255) / 256, 256>>>(v_idx, e_idx);
    k_agg    <<<(N_EDGES * 32 + 255) / 256, 256>>>();
    k_gemm   <<<((N_EDGES / 4) * 32 + 255) / 256, 256>>>(Wm, bias);
    k_gather <<<(N_NODES * 32 + 255) / 256, 256>>>(out);
}